// round 16
// baseline (speedup 1.0000x reference)
#include <cuda_runtime.h>
#include <cuda_fp16.h>
#include <cstdint>
#include <cstddef>

#define HEADS 8
#define NWIN  2048
#define MROWS (NWIN * 64)                   // 131072 token rows
#define BNC   ((size_t)MROWS * 256)         // 33,554,432 output elems per tensor

// ---------------- scratch (device globals; no allocation allowed) ----------
__device__ __half g_wt[2][1024 * 256];              // QKV weights, [src][col][k]
__device__ __half g_wpt[2][256 * 512];              // out-proj weights, [w][n][k]
__device__ __half g_qkv[(size_t)NWIN * 2 * 4 * HEADS * 64 * 32];  // head tiles
__device__ __half g_attv[(size_t)MROWS * 512];      // [cross_v | self_v]
__device__ __half g_atth[(size_t)MROWS * 512];      // [cross_h | self_h]
// bias in MMA C-fragment order, pre-scaled by log2(e):
//   [a][h][mt][hf] blocks of 256 float4; float4 #i of lane L = sacc[nt=i][r]
__device__ float  g_bias[4 * HEADS * 64 * 64];      // 512 KB

// ---------------- helpers ---------------------------------------------------
__device__ __forceinline__ uint32_t smem_u32(const void* p) {
    uint32_t a;
    asm("{ .reg .u64 t; cvta.to.shared.u64 t, %1; cvt.u32.u64 %0, t; }" : "=r"(a) : "l"(p));
    return a;
}
#define CP_ASYNC16(dst, src) \
    asm volatile("cp.async.cg.shared.global [%0], [%1], 16;" :: "r"(dst), "l"(src))
#define CP_COMMIT() asm volatile("cp.async.commit_group;" ::: "memory")
#define CP_WAIT(n)  asm volatile("cp.async.wait_group %0;" :: "n"(n) : "memory")

#define LDSM_X4(r, addr) \
    asm volatile("ldmatrix.sync.aligned.m8n8.x4.shared.b16 {%0,%1,%2,%3}, [%4];" \
        : "=r"((r)[0]), "=r"((r)[1]), "=r"((r)[2]), "=r"((r)[3]) : "r"(addr))

#define LDSM_X4_T(r, addr) \
    asm volatile("ldmatrix.sync.aligned.m8n8.x4.trans.shared.b16 {%0,%1,%2,%3}, [%4];" \
        : "=r"((r)[0]), "=r"((r)[1]), "=r"((r)[2]), "=r"((r)[3]) : "r"(addr))

#define MMA_16816(c, a, b0, b1) \
    asm volatile("mma.sync.aligned.m16n8k16.row.col.f32.f16.f16.f32 " \
        "{%0,%1,%2,%3}, {%4,%5,%6,%7}, {%8,%9}, {%0,%1,%2,%3};" \
        : "+f"((c)[0]), "+f"((c)[1]), "+f"((c)[2]), "+f"((c)[3]) \
        : "r"((a)[0]), "r"((a)[1]), "r"((a)[2]), "r"((a)[3]), "r"(b0), "r"(b1))

// split a float pair into fp16 high + fp16 low (residual) packs
__device__ __forceinline__ void pack_hl(float x, float y, uint32_t& hi, uint32_t& lo) {
    __half2 h = __floats2half2_rn(x, y);
    float2 r = __half22float2(h);
    __half2 l = __floats2half2_rn(x - r.x, y - r.y);
    hi = *(uint32_t*)&h;
    lo = *(uint32_t*)&l;
}

#define L2E_CONST 1.4426950408889634f

// ---------------- merged prep kernel -----------------------------------------
// [0, 524288)          : g_wt transpose+fp16
// [524288, 786432)     : g_wpt transpose+fp16
// [786432, 917504)     : bias gather -> fragment layout, pre-scaled by log2e
__global__ void prep_kernel(const float* __restrict__ Ws, const float* __restrict__ We,
                            const float* __restrict__ Wpv, const float* __restrict__ Wph,
                            const float* __restrict__ tcv, const float* __restrict__ tsv,
                            const float* __restrict__ tch, const float* __restrict__ tsh,
                            const int* __restrict__ rpi) {
    int idx = blockIdx.x * 256 + threadIdx.x;
    if (idx < 524288) {
        int k = idx & 255, c = (idx >> 8) & 1023, src = idx >> 18;
        const float* W = src ? We : Ws;
        g_wt[src][c * 256 + k] = __float2half_rn(W[(size_t)k * 1024 + c]);
    } else if (idx < 786432) {
        int e = idx - 524288;
        int k = e & 511, n = (e >> 9) & 255, w = e >> 17;
        const float* W = w ? Wph : Wpv;
        g_wpt[w][n * 512 + k] = __float2half_rn(W[(size_t)k * 256 + n]);
    } else {
        int e = idx - 786432;                       // 131072
        int r    = e & 3;
        int lane = (e >> 2) & 31;
        int nt   = (e >> 7) & 7;
        int hf   = (e >> 10) & 1;
        int mt   = (e >> 11) & 1;
        int h    = (e >> 12) & 7;
        int a    = e >> 15;
        const float* tab = (a == 0) ? tcv : (a == 1) ? tsv : (a == 2) ? tch : tsh;
        int row = hf * 32 + mt * 16 + (lane >> 2) + ((r & 2) ? 8 : 0);
        int col = nt * 8 + (lane & 3) * 2 + (r & 1);
        g_bias[e] = tab[rpi[row * 64 + col] * HEADS + h] * L2E_CONST;
    }
}

// ---------------- QKV projection GEMM (round-9 proven, frozen) ---------------
#define SM_QKV (65536 + 131072 + 4096)

__global__ __launch_bounds__(512, 1)
void qkv_gemm(const float* __restrict__ input_x, const float* __restrict__ state_x,
              const float* __restrict__ bs, const float* __restrict__ be) {
    extern __shared__ __half smh[];
    __half* SA = smh;                               // 32768 halves
    __half* SB = smh + 32768;                       // 2 x 32768 halves
    float*  SBias = (float*)(smh + 32768 + 65536);  // 1024 floats

    const int tid = threadIdx.x, w = tid >> 5, lane = tid & 31;
    const int mb = blockIdx.x, src = blockIdx.y;
    const int wm = (w >> 2) * 32, wn = (w & 3) * 32;
    const int gid = lane >> 2, tig = lane & 3;

    const float4* X4 = (const float4*)(src ? input_x : state_x);
    #pragma unroll
    for (int i = 0; i < 8; i++) {
        int ch = tid + i * 512;                     // 4096 chunks of 8 halves
        int r = ch >> 5, c = ch & 31;
        size_t gsrc = ((size_t)(mb * 128 + r) * 256 + c * 8) >> 2;
        float4 v0 = X4[gsrc], v1 = X4[gsrc + 1];
        __half2 h0 = __floats2half2_rn(v0.x, v0.y), h1 = __floats2half2_rn(v0.z, v0.w);
        __half2 h2 = __floats2half2_rn(v1.x, v1.y), h3 = __floats2half2_rn(v1.z, v1.w);
        uint4 u;
        u.x = *(uint32_t*)&h0; u.y = *(uint32_t*)&h1;
        u.z = *(uint32_t*)&h2; u.w = *(uint32_t*)&h3;
        *(uint4*)(SA + r * 256 + ((c ^ (r & 7)) << 3)) = u;
    }
    {
        const float* bv = src ? be : bs;
        #pragma unroll
        for (int i = 0; i < 2; i++) SBias[tid + i * 512] = bv[tid + i * 512];
    }

    const __half* Bsrc = g_wt[src];
    auto issueB = [&](int s, int nb) {
        __half* sb = SB + s * 32768;
        #pragma unroll
        for (int i = 0; i < 8; i++) {
            int ch = tid + i * 512;                 // 4096 chunks of 16B
            int r = ch >> 5, c = ch & 31;
            uint32_t d = smem_u32(sb + r * 256 + ((c ^ (r & 7)) << 3));
            CP_ASYNC16(d, Bsrc + (size_t)(nb * 128 + r) * 256 + c * 8);
        }
        CP_COMMIT();
    };
    issueB(0, 0);

    const float kscale = 0.17677669529663687f;
    const float m2 = (src ? 1.0f : kscale) * L2E_CONST;            // qsv / qev
    const float m3 = (src ? kscale : kscale * kscale) * L2E_CONST; // qsh / qeh

    uint32_t baseA = smem_u32(SA);

    #pragma unroll 1
    for (int nb = 0; nb < 8; nb++) {
        int s = nb & 1;
        if (nb + 1 < 8) {
            issueB(s ^ 1, nb + 1);
            CP_WAIT(1);
        } else {
            CP_WAIT(0);
        }
        __syncthreads();
        uint32_t baseB = smem_u32(SB + s * 32768);

        float acc[2][4][4];
        #pragma unroll
        for (int t = 0; t < 2; t++)
            #pragma unroll
            for (int j = 0; j < 4; j++)
                #pragma unroll
                for (int r = 0; r < 4; r++) acc[t][j][r] = 0.0f;

        uint32_t af[2][2][4], bf[2][2][4];
        auto load_frags = [&](int ks, int buf) {
            #pragma unroll
            for (int t = 0; t < 2; t++) {
                int row = wm + t * 16 + (lane & 15);
                int kc8 = ks * 2 + (lane >> 4);
                LDSM_X4(af[buf][t], baseA + ((row * 256 + ((kc8 ^ (row & 7)) << 3)) << 1));
            }
            #pragma unroll
            for (int p = 0; p < 2; p++) {
                int n   = wn + p * 16 + ((lane >> 4) << 3) + (lane & 7);
                int kc8 = ks * 2 + ((lane >> 3) & 1);
                LDSM_X4(bf[buf][p], baseB + ((n * 256 + ((kc8 ^ (n & 7)) << 3)) << 1));
            }
        };
        load_frags(0, 0);
        #pragma unroll
        for (int ks = 0; ks < 16; ks++) {
            int cb = ks & 1;
            if (ks < 15) load_frags(ks + 1, cb ^ 1);
            #pragma unroll
            for (int t = 0; t < 2; t++)
                #pragma unroll
                for (int j = 0; j < 4; j++)
                    MMA_16816(acc[t][j], af[cb][t],
                              bf[cb][j >> 1][(j & 1) * 2], bf[cb][j >> 1][(j & 1) * 2 + 1]);
        }

        #pragma unroll
        for (int t = 0; t < 2; t++)
            #pragma unroll
            for (int j = 0; j < 4; j++) {
                int nglob = nb * 128 + wn + j * 8 + tig * 2;   // 0..1023
                int f = nglob >> 8, h = (nglob >> 5) & 7, d = nglob & 31;
                float mult = (f == 2) ? m2 : (f == 3) ? m3 : 1.0f;
                float b0 = SBias[nglob], b1 = SBias[nglob + 1];
                #pragma unroll
                for (int rr = 0; rr < 2; rr++) {
                    int m = mb * 128 + wm + t * 16 + gid + rr * 8;
                    int b = m >> 6, ntok = m & 63;
                    size_t tile = ((((size_t)b * 2 + src) * 4 + f) * 8 + h) * 2048;
                    __half2 hv = __floats2half2_rn((acc[t][j][rr * 2] + b0) * mult,
                                                   (acc[t][j][rr * 2 + 1] + b1) * mult);
                    *(__half2*)(g_qkv + tile + ntok * 32 + d) = hv;
                }
            }
        __syncthreads();
    }
}

// ---------------- attention kernel (R15 measured-best, frozen) --------------
#define SM_ATT (2 * 8 * 2048 * 2)

__global__ __launch_bounds__(256, 3)
void attn_kernel() {
    extern __shared__ __half smh[];
    const int b = blockIdx.x, tid = threadIdx.x;
    const int w = tid >> 5, lane = tid & 31;
    const int gid = lane >> 2, tig = lane & 3;
    const int a = w >> 1, hf = w & 1;

    const int qt = (a == 0) ? 2 : (a == 1) ? 6 : (a == 2) ? 7 : 3;
    const int kt = (a == 0 || a == 3) ? 0 : 4;
    const int vt = kt + 1;
    __half* dst0 = (a <= 1) ? g_attv : g_atth;
    const int cbase = (a == 1 || a == 3) ? 256 : 0;

    auto stage = [&](int st, int h) {
        #pragma unroll
        for (int i = 0; i < 8; i++) {
            int ch = tid + i * 256;             // 2048 chunks of 16B
            int t = ch >> 8, c = ch & 255;
            const __half* src = g_qkv +
                ((((size_t)b * 2 + (t >> 2)) * 4 + (t & 3)) * 8 + h) * 2048 + c * 8;
            int r = c >> 2, c4 = c & 3;
            uint32_t off = r * 32 + ((c4 ^ ((r >> 1) & 3)) << 3);
            CP_ASYNC16(smem_u32(smh + (st * 8 + t) * 2048 + off), src);
        }
    };

    stage(0, 0);
    CP_COMMIT();

    #pragma unroll 1
    for (int h = 0; h < HEADS; h++) {
        int st = h & 1;
        if (h < 7) {
            stage(st ^ 1, h + 1);
            CP_COMMIT();
            CP_WAIT(1);
        } else {
            CP_WAIT(0);
        }
        __syncthreads();

        uint32_t Qb = smem_u32(smh + (st * 8 + qt) * 2048);
        uint32_t Kb = smem_u32(smh + (st * 8 + kt) * 2048);
        uint32_t Vb = smem_u32(smh + (st * 8 + vt) * 2048);

        #pragma unroll 1
        for (int mt = 0; mt < 2; mt++) {
            const int rbase = hf * 32 + mt * 16;
            const int r0 = rbase + gid;

            float sacc[8][4];
            {
                const float4* Bf = (const float4*)g_bias +
                    (size_t)((((a * 8 + h) * 2 + mt) * 2 + hf) * 256 + lane);
                #pragma unroll
                for (int i = 0; i < 8; i++) {
                    float4 v = Bf[i * 32];
                    sacc[i][0] = v.x; sacc[i][1] = v.y;
                    sacc[i][2] = v.z; sacc[i][3] = v.w;
                }
            }
            #pragma unroll
            for (int kk = 0; kk < 2; kk++) {
                uint32_t af[4];
                {
                    int row = rbase + (lane & 15);
                    int c4 = kk * 2 + (lane >> 4);
                    LDSM_X4(af, Qb + ((row * 32 + ((c4 ^ ((row >> 1) & 3)) << 3)) << 1));
                }
                #pragma unroll
                for (int ntp = 0; ntp < 4; ntp++) {
                    uint32_t bf[4];
                    int row = ntp * 16 + ((lane >> 4) << 3) + (lane & 7);
                    int c4 = kk * 2 + ((lane >> 3) & 1);
                    LDSM_X4(bf, Kb + ((row * 32 + ((c4 ^ ((row >> 1) & 3)) << 3)) << 1));
                    MMA_16816(sacc[ntp * 2],     af, bf[0], bf[1]);
                    MMA_16816(sacc[ntp * 2 + 1], af, bf[2], bf[3]);
                }
            }

            float mx0 = -1e30f, mx1 = -1e30f;
            #pragma unroll
            for (int nt = 0; nt < 8; nt++) {
                mx0 = fmaxf(mx0, fmaxf(sacc[nt][0], sacc[nt][1]));
                mx1 = fmaxf(mx1, fmaxf(sacc[nt][2], sacc[nt][3]));
            }
            mx0 = fmaxf(mx0, __shfl_xor_sync(0xffffffffu, mx0, 1));
            mx0 = fmaxf(mx0, __shfl_xor_sync(0xffffffffu, mx0, 2));
            mx1 = fmaxf(mx1, __shfl_xor_sync(0xffffffffu, mx1, 1));
            mx1 = fmaxf(mx1, __shfl_xor_sync(0xffffffffu, mx1, 2));
            float sum0 = 0.0f, sum1 = 0.0f;
            #pragma unroll
            for (int nt = 0; nt < 8; nt++) {
                sacc[nt][0] = exp2f(sacc[nt][0] - mx0);
                sacc[nt][1] = exp2f(sacc[nt][1] - mx0);
                sacc[nt][2] = exp2f(sacc[nt][2] - mx1);
                sacc[nt][3] = exp2f(sacc[nt][3] - mx1);
                sum0 += sacc[nt][0] + sacc[nt][1];
                sum1 += sacc[nt][2] + sacc[nt][3];
            }
            sum0 += __shfl_xor_sync(0xffffffffu, sum0, 1);
            sum0 += __shfl_xor_sync(0xffffffffu, sum0, 2);
            sum1 += __shfl_xor_sync(0xffffffffu, sum1, 1);
            sum1 += __shfl_xor_sync(0xffffffffu, sum1, 2);
            float inv0 = __fdividef(1.0f, sum0);
            float inv1 = __fdividef(1.0f, sum1);

            float oacc[4][4];
            #pragma unroll
            for (int n4 = 0; n4 < 4; n4++)
                #pragma unroll
                for (int r = 0; r < 4; r++) oacc[n4][r] = 0.0f;

            #pragma unroll
            for (int kk = 0; kk < 4; kk++) {
                uint32_t bf[2][4];
                #pragma unroll
                for (int ntp = 0; ntp < 2; ntp++) {
                    int row = kk * 16 + ((lane >> 3) & 1) * 8 + (lane & 7);
                    int c4 = ntp * 2 + ((lane >> 4) & 1);
                    LDSM_X4_T(bf[ntp], Vb + ((row * 32 + ((c4 ^ ((row >> 1) & 3)) << 3)) << 1));
                }
                uint32_t ah[4], al[4];
                pack_hl(sacc[2 * kk][0],     sacc[2 * kk][1],     ah[0], al[0]);
                pack_hl(sacc[2 * kk][2],     sacc[2 * kk][3],     ah[1], al[1]);
                pack_hl(sacc[2 * kk + 1][0], sacc[2 * kk + 1][1], ah[2], al[2]);
                pack_hl(sacc[2 * kk + 1][2], sacc[2 * kk + 1][3], ah[3], al[3]);
                #pragma unroll
                for (int n4 = 0; n4 < 4; n4++) {
                    MMA_16816(oacc[n4], ah, bf[n4 >> 1][(n4 & 1) * 2], bf[n4 >> 1][(n4 & 1) * 2 + 1]);
                    MMA_16816(oacc[n4], al, bf[n4 >> 1][(n4 & 1) * 2], bf[n4 >> 1][(n4 & 1) * 2 + 1]);
                }
            }

            size_t rowg = (size_t)b * 64 + r0;
            #pragma unroll
            for (int n4 = 0; n4 < 4; n4++) {
                int col = cbase + (h << 5) + n4 * 8 + tig * 2;
                __half2 v0 = __floats2half2_rn(oacc[n4][0] * inv0, oacc[n4][1] * inv0);
                __half2 v1 = __floats2half2_rn(oacc[n4][2] * inv1, oacc[n4][3] * inv1);
                *(__half2*)(dst0 + rowg * 512 + col)       = v0;
                *(__half2*)(dst0 + (rowg + 8) * 512 + col) = v1;
            }
        }
        __syncthreads();
    }
}

// ---------------- output projection GEMM (3-stage cp.async pipeline) ---------
#define SM_OUT (3 * (16384 + 32768))

__global__ __launch_bounds__(512, 1)
void out_gemm(const float* __restrict__ bpv, const float* __restrict__ bph,
              float* __restrict__ out) {
    extern __shared__ __half smo[];
    __half* SA = smo;                  // 3 x 8192 halves
    __half* SB = smo + 3 * 8192;       // 3 x 16384 halves
    const int mb = blockIdx.x, which = blockIdx.y;
    const __half* A = which ? g_atth : g_attv;
    const __half* B = g_wpt[which];
    const float* bp = which ? bph : bpv;
    float* dst = out + (size_t)which * BNC;

    const int tid = threadIdx.x, w = tid >> 5, lane = tid & 31;
    const int wm = (w >> 2) * 32, wn = (w & 3) * 64;

    float acc[2][8][4];
    #pragma unroll
    for (int t = 0; t < 2; t++)
        #pragma unroll
        for (int j = 0; j < 8; j++)
            #pragma unroll
            for (int r = 0; r < 4; r++) acc[t][j][r] = 0.0f;

    auto issue = [&](int s, int kc) {
        __half* sa = SA + s * 8192;
        __half* sb = SB + s * 16384;
        #pragma unroll
        for (int i = 0; i < 2; i++) {            // A: 1024 chunks of 16B
            int ch = tid + i * 512, r = ch >> 3, k8 = ch & 7;
            uint32_t d = smem_u32(sa + r * 64 + ((k8 ^ (r & 7)) << 3));
            CP_ASYNC16(d, A + (size_t)(mb * 128 + r) * 512 + kc * 64 + k8 * 8);
        }
        #pragma unroll
        for (int i = 0; i < 4; i++) {            // B: 2048 chunks of 16B
            int ch = tid + i * 512, r = ch >> 3, k8 = ch & 7;
            uint32_t d = smem_u32(sb + r * 64 + ((k8 ^ (r & 7)) << 3));
            CP_ASYNC16(d, B + (size_t)r * 512 + kc * 64 + k8 * 8);
        }
        CP_COMMIT();
    };
    issue(0, 0);
    issue(1, 1);

    #pragma unroll 1
    for (int kc = 0; kc < 8; kc++) {
        if (kc + 2 < 8) {
            issue((kc + 2) % 3, kc + 2);
            CP_WAIT(2);
        } else if (kc + 1 < 8) {
            CP_WAIT(1);
        } else {
            CP_WAIT(0);
        }
        __syncthreads();

        int s = kc % 3;
        uint32_t baseA = smem_u32(SA + s * 8192);
        uint32_t baseB = smem_u32(SB + s * 16384);
        #pragma unroll
        for (int ks = 0; ks < 4; ks++) {
            uint32_t af[2][4], bf[4][4];
            #pragma unroll
            for (int t = 0; t < 2; t++) {
                int row = wm + t * 16 + (lane & 15);
                int kc8 = ks * 2 + (lane >> 4);
                LDSM_X4(af[t], baseA + ((row * 64 + ((kc8 ^ (row & 7)) << 3)) << 1));
            }
            #pragma unroll
            for (int p = 0; p < 4; p++) {
                int n   = wn + p * 16 + ((lane >> 4) << 3) + (lane & 7);
                int kc8 = ks * 2 + ((lane >> 3) & 1);
                LDSM_X4(bf[p], baseB + ((n * 64 + ((kc8 ^ (n & 7)) << 3)) << 1));
            }
            #pragma unroll
            for (int t = 0; t < 2; t++)
                #pragma unroll
                for (int j = 0; j < 8; j++)
                    MMA_16816(acc[t][j], af[t],
                              bf[j >> 1][(j & 1) * 2], bf[j >> 1][(j & 1) * 2 + 1]);
        }
        __syncthreads();
    }

    const int gid = lane >> 2, tig = lane & 3;
    #pragma unroll
    for (int t = 0; t < 2; t++)
        #pragma unroll
        for (int j = 0; j < 8; j++) {
            int n = wn + j * 8 + tig * 2;             // 0..255
            float b0 = bp[n], b1 = bp[n + 1];
            #pragma unroll
            for (int rr = 0; rr < 2; rr++) {
                int m = mb * 128 + wm + t * 16 + gid + rr * 8;
                float2 v = make_float2(acc[t][j][rr * 2] + b0,
                                       acc[t][j][rr * 2 + 1] + b1);
                *(float2*)(dst + (size_t)m * 256 + n) = v;
            }
        }
}

// ---------------- launch -----------------------------------------------------
// 4 launches: prep, qkv, attn, out — out_gemm is the 4th (ncu capture target).
extern "C" void kernel_launch(void* const* d_in, const int* in_sizes, int n_in,
                              void* d_out, int out_size) {
    const float* input_x = (const float*)d_in[0];
    const float* state_x = (const float*)d_in[1];
    const float* Ws  = (const float*)d_in[2];
    const float* bs  = (const float*)d_in[3];
    const float* We  = (const float*)d_in[4];
    const float* be  = (const float*)d_in[5];
    const float* Wpv = (const float*)d_in[6];
    const float* bpv = (const float*)d_in[7];
    const float* Wph = (const float*)d_in[8];
    const float* bph = (const float*)d_in[9];
    const float* tcv = (const float*)d_in[10];
    const float* tsv = (const float*)d_in[11];
    const float* tch = (const float*)d_in[12];
    const float* tsh = (const float*)d_in[13];
    const int*   rpi = (const int*)d_in[14];
    float* out = (float*)d_out;

    cudaFuncSetAttribute(qkv_gemm, cudaFuncAttributeMaxDynamicSharedMemorySize, SM_QKV);
    cudaFuncSetAttribute(attn_kernel, cudaFuncAttributeMaxDynamicSharedMemorySize, SM_ATT);
    cudaFuncSetAttribute(out_gemm, cudaFuncAttributeMaxDynamicSharedMemorySize, SM_OUT);

    prep_kernel<<<3584, 256>>>(Ws, We, Wpv, Wph, tcv, tsv, tch, tsh, rpi);  // 1
    qkv_gemm<<<dim3(1024, 2), 512, SM_QKV>>>(input_x, state_x, bs, be);     // 2
    attn_kernel<<<NWIN, 256, SM_ATT>>>();                                   // 3
    out_gemm<<<dim3(1024, 2), 512, SM_OUT>>>(bpv, bph, out);                // 4 <- ncu
}

// round 17
// speedup vs baseline: 1.0396x; 1.0396x over previous
#include <cuda_runtime.h>
#include <cuda_fp16.h>
#include <cstdint>
#include <cstddef>

#define HEADS 8
#define NWIN  2048
#define MROWS (NWIN * 64)                   // 131072 token rows
#define BNC   ((size_t)MROWS * 256)         // 33,554,432 output elems per tensor

// ---------------- scratch (device globals; no allocation allowed) ----------
__device__ __half g_wt[2][1024 * 256];              // QKV weights, [src][col][k]
__device__ __half g_wpt[2][256 * 512];              // out-proj weights, k-permuted
__device__ __half g_qkv[(size_t)NWIN * 2 * 4 * HEADS * 64 * 32];  // head tiles
__device__ __half g_attv[(size_t)MROWS * 512];      // [cross_v | self_v], k-permuted
__device__ __half g_atth[(size_t)MROWS * 512];      // [cross_h | self_h], k-permuted
// bias in MMA C-fragment order, pre-scaled by log2(e)
__device__ float  g_bias[4 * HEADS * 64 * 64];      // 512 KB

// ---------------- helpers ---------------------------------------------------
__device__ __forceinline__ uint32_t smem_u32(const void* p) {
    uint32_t a;
    asm("{ .reg .u64 t; cvta.to.shared.u64 t, %1; cvt.u32.u64 %0, t; }" : "=r"(a) : "l"(p));
    return a;
}
#define CP_ASYNC16(dst, src) \
    asm volatile("cp.async.cg.shared.global [%0], [%1], 16;" :: "r"(dst), "l"(src))
#define CP_COMMIT() asm volatile("cp.async.commit_group;" ::: "memory")
#define CP_WAIT(n)  asm volatile("cp.async.wait_group %0;" :: "n"(n) : "memory")

#define LDSM_X4(r, addr) \
    asm volatile("ldmatrix.sync.aligned.m8n8.x4.shared.b16 {%0,%1,%2,%3}, [%4];" \
        : "=r"((r)[0]), "=r"((r)[1]), "=r"((r)[2]), "=r"((r)[3]) : "r"(addr))

#define LDSM_X4_T(r, addr) \
    asm volatile("ldmatrix.sync.aligned.m8n8.x4.trans.shared.b16 {%0,%1,%2,%3}, [%4];" \
        : "=r"((r)[0]), "=r"((r)[1]), "=r"((r)[2]), "=r"((r)[3]) : "r"(addr))

#define MMA_16816(c, a, b0, b1) \
    asm volatile("mma.sync.aligned.m16n8k16.row.col.f32.f16.f16.f32 " \
        "{%0,%1,%2,%3}, {%4,%5,%6,%7}, {%8,%9}, {%0,%1,%2,%3};" \
        : "+f"((c)[0]), "+f"((c)[1]), "+f"((c)[2]), "+f"((c)[3]) \
        : "r"((a)[0]), "r"((a)[1]), "r"((a)[2]), "r"((a)[3]), "r"(b0), "r"(b1))

// split a float pair into fp16 high + fp16 low (residual) packs
__device__ __forceinline__ void pack_hl(float x, float y, uint32_t& hi, uint32_t& lo) {
    __half2 h = __floats2half2_rn(x, y);
    float2 r = __half22float2(h);
    __half2 l = __floats2half2_rn(x - r.x, y - r.y);
    hi = *(uint32_t*)&h;
    lo = *(uint32_t*)&l;
}

#define L2E_CONST 1.4426950408889634f

// ---------------- prep kernel A: g_wt + bias ----------------------------------
// [0, 524288)      : g_wt transpose+fp16
// [524288, 655360) : bias gather -> fragment layout, pre-scaled by log2e
__global__ void prep_ab(const float* __restrict__ Ws, const float* __restrict__ We,
                        const float* __restrict__ tcv, const float* __restrict__ tsv,
                        const float* __restrict__ tch, const float* __restrict__ tsh,
                        const int* __restrict__ rpi) {
    int idx = blockIdx.x * 256 + threadIdx.x;
    if (idx < 524288) {
        int k = idx & 255, c = (idx >> 8) & 1023, src = idx >> 18;
        const float* W = src ? We : Ws;
        g_wt[src][c * 256 + k] = __float2half_rn(W[(size_t)k * 1024 + c]);
    } else {
        int e = idx - 524288;                       // 131072
        int r    = e & 3;
        int lane = (e >> 2) & 31;
        int nt   = (e >> 7) & 7;
        int hf   = (e >> 10) & 1;
        int mt   = (e >> 11) & 1;
        int h    = (e >> 12) & 7;
        int a    = e >> 15;
        const float* tab = (a == 0) ? tcv : (a == 1) ? tsv : (a == 2) ? tch : tsh;
        int row = hf * 32 + mt * 16 + (lane >> 2) + ((r & 2) ? 8 : 0);
        int col = nt * 8 + (lane & 3) * 2 + (r & 1);
        g_bias[e] = tab[rpi[row * 64 + col] * HEADS + h] * L2E_CONST;
    }
}

// ---------------- prep kernel B: g_wpt with k-permutation --------------------
// Within each 32-wide k-block: stored k' = tig*8 + n4*2 + bit corresponds to
// actual k = n4*8 + tig*2 + bit (matches attn's packed STG.128 layout).
__global__ void prep_c(const float* __restrict__ Wpv, const float* __restrict__ Wph) {
    int idx = blockIdx.x * 256 + threadIdx.x;          // 262144
    int k = idx & 511, n = (idx >> 9) & 255, w = idx >> 17;
    int t2 = (k >> 3) & 3, n4 = (k >> 1) & 3, bit = k & 1;
    int kact = (k & ~31) | (n4 * 8 + t2 * 2 + bit);
    const float* W = w ? Wph : Wpv;
    g_wpt[w][n * 512 + k] = __float2half_rn(W[(size_t)kact * 256 + n]);
}

// ---------------- QKV projection GEMM (round-9 proven, frozen) ---------------
#define SM_QKV (65536 + 131072 + 4096)

__global__ __launch_bounds__(512, 1)
void qkv_gemm(const float* __restrict__ input_x, const float* __restrict__ state_x,
              const float* __restrict__ bs, const float* __restrict__ be) {
    extern __shared__ __half smh[];
    __half* SA = smh;                               // 32768 halves
    __half* SB = smh + 32768;                       // 2 x 32768 halves
    float*  SBias = (float*)(smh + 32768 + 65536);  // 1024 floats

    const int tid = threadIdx.x, w = tid >> 5, lane = tid & 31;
    const int mb = blockIdx.x, src = blockIdx.y;
    const int wm = (w >> 2) * 32, wn = (w & 3) * 32;
    const int gid = lane >> 2, tig = lane & 3;

    const float4* X4 = (const float4*)(src ? input_x : state_x);
    #pragma unroll
    for (int i = 0; i < 8; i++) {
        int ch = tid + i * 512;                     // 4096 chunks of 8 halves
        int r = ch >> 5, c = ch & 31;
        size_t gsrc = ((size_t)(mb * 128 + r) * 256 + c * 8) >> 2;
        float4 v0 = X4[gsrc], v1 = X4[gsrc + 1];
        __half2 h0 = __floats2half2_rn(v0.x, v0.y), h1 = __floats2half2_rn(v0.z, v0.w);
        __half2 h2 = __floats2half2_rn(v1.x, v1.y), h3 = __floats2half2_rn(v1.z, v1.w);
        uint4 u;
        u.x = *(uint32_t*)&h0; u.y = *(uint32_t*)&h1;
        u.z = *(uint32_t*)&h2; u.w = *(uint32_t*)&h3;
        *(uint4*)(SA + r * 256 + ((c ^ (r & 7)) << 3)) = u;
    }
    {
        const float* bv = src ? be : bs;
        #pragma unroll
        for (int i = 0; i < 2; i++) SBias[tid + i * 512] = bv[tid + i * 512];
    }

    const __half* Bsrc = g_wt[src];
    auto issueB = [&](int s, int nb) {
        __half* sb = SB + s * 32768;
        #pragma unroll
        for (int i = 0; i < 8; i++) {
            int ch = tid + i * 512;                 // 4096 chunks of 16B
            int r = ch >> 5, c = ch & 31;
            uint32_t d = smem_u32(sb + r * 256 + ((c ^ (r & 7)) << 3));
            CP_ASYNC16(d, Bsrc + (size_t)(nb * 128 + r) * 256 + c * 8);
        }
        CP_COMMIT();
    };
    issueB(0, 0);

    const float kscale = 0.17677669529663687f;
    const float m2 = (src ? 1.0f : kscale) * L2E_CONST;            // qsv / qev
    const float m3 = (src ? kscale : kscale * kscale) * L2E_CONST; // qsh / qeh

    uint32_t baseA = smem_u32(SA);

    #pragma unroll 1
    for (int nb = 0; nb < 8; nb++) {
        int s = nb & 1;
        if (nb + 1 < 8) {
            issueB(s ^ 1, nb + 1);
            CP_WAIT(1);
        } else {
            CP_WAIT(0);
        }
        __syncthreads();
        uint32_t baseB = smem_u32(SB + s * 32768);

        float acc[2][4][4];
        #pragma unroll
        for (int t = 0; t < 2; t++)
            #pragma unroll
            for (int j = 0; j < 4; j++)
                #pragma unroll
                for (int r = 0; r < 4; r++) acc[t][j][r] = 0.0f;

        uint32_t af[2][2][4], bf[2][2][4];
        auto load_frags = [&](int ks, int buf) {
            #pragma unroll
            for (int t = 0; t < 2; t++) {
                int row = wm + t * 16 + (lane & 15);
                int kc8 = ks * 2 + (lane >> 4);
                LDSM_X4(af[buf][t], baseA + ((row * 256 + ((kc8 ^ (row & 7)) << 3)) << 1));
            }
            #pragma unroll
            for (int p = 0; p < 2; p++) {
                int n   = wn + p * 16 + ((lane >> 4) << 3) + (lane & 7);
                int kc8 = ks * 2 + ((lane >> 3) & 1);
                LDSM_X4(bf[buf][p], baseB + ((n * 256 + ((kc8 ^ (n & 7)) << 3)) << 1));
            }
        };
        load_frags(0, 0);
        #pragma unroll
        for (int ks = 0; ks < 16; ks++) {
            int cb = ks & 1;
            if (ks < 15) load_frags(ks + 1, cb ^ 1);
            #pragma unroll
            for (int t = 0; t < 2; t++)
                #pragma unroll
                for (int j = 0; j < 4; j++)
                    MMA_16816(acc[t][j], af[cb][t],
                              bf[cb][j >> 1][(j & 1) * 2], bf[cb][j >> 1][(j & 1) * 2 + 1]);
        }

        #pragma unroll
        for (int t = 0; t < 2; t++)
            #pragma unroll
            for (int j = 0; j < 4; j++) {
                int nglob = nb * 128 + wn + j * 8 + tig * 2;   // 0..1023
                int f = nglob >> 8, h = (nglob >> 5) & 7, d = nglob & 31;
                float mult = (f == 2) ? m2 : (f == 3) ? m3 : 1.0f;
                float b0 = SBias[nglob], b1 = SBias[nglob + 1];
                #pragma unroll
                for (int rr = 0; rr < 2; rr++) {
                    int m = mb * 128 + wm + t * 16 + gid + rr * 8;
                    int b = m >> 6, ntok = m & 63;
                    size_t tile = ((((size_t)b * 2 + src) * 4 + f) * 8 + h) * 2048;
                    __half2 hv = __floats2half2_rn((acc[t][j][rr * 2] + b0) * mult,
                                                   (acc[t][j][rr * 2 + 1] + b1) * mult);
                    *(__half2*)(g_qkv + tile + ntok * 32 + d) = hv;
                }
            }
        __syncthreads();
    }
}

// ---------------- attention kernel (R15 + packed STG.128 epilogue) ----------
#define SM_ATT (2 * 8 * 2048 * 2)

__global__ __launch_bounds__(256, 3)
void attn_kernel() {
    extern __shared__ __half smh[];
    const int b = blockIdx.x, tid = threadIdx.x;
    const int w = tid >> 5, lane = tid & 31;
    const int gid = lane >> 2, tig = lane & 3;
    const int a = w >> 1, hf = w & 1;

    const int qt = (a == 0) ? 2 : (a == 1) ? 6 : (a == 2) ? 7 : 3;
    const int kt = (a == 0 || a == 3) ? 0 : 4;
    const int vt = kt + 1;
    __half* dst0 = (a <= 1) ? g_attv : g_atth;
    const int cbase = (a == 1 || a == 3) ? 256 : 0;

    auto stage = [&](int st, int h) {
        #pragma unroll
        for (int i = 0; i < 8; i++) {
            int ch = tid + i * 256;             // 2048 chunks of 16B
            int t = ch >> 8, c = ch & 255;
            const __half* src = g_qkv +
                ((((size_t)b * 2 + (t >> 2)) * 4 + (t & 3)) * 8 + h) * 2048 + c * 8;
            int r = c >> 2, c4 = c & 3;
            uint32_t off = r * 32 + ((c4 ^ ((r >> 1) & 3)) << 3);
            CP_ASYNC16(smem_u32(smh + (st * 8 + t) * 2048 + off), src);
        }
    };

    stage(0, 0);
    CP_COMMIT();

    #pragma unroll 1
    for (int h = 0; h < HEADS; h++) {
        int st = h & 1;
        if (h < 7) {
            stage(st ^ 1, h + 1);
            CP_COMMIT();
            CP_WAIT(1);
        } else {
            CP_WAIT(0);
        }
        __syncthreads();

        uint32_t Qb = smem_u32(smh + (st * 8 + qt) * 2048);
        uint32_t Kb = smem_u32(smh + (st * 8 + kt) * 2048);
        uint32_t Vb = smem_u32(smh + (st * 8 + vt) * 2048);

        #pragma unroll 1
        for (int mt = 0; mt < 2; mt++) {
            const int rbase = hf * 32 + mt * 16;
            const int r0 = rbase + gid;

            float sacc[8][4];
            {
                const float4* Bf = (const float4*)g_bias +
                    (size_t)((((a * 8 + h) * 2 + mt) * 2 + hf) * 256 + lane);
                #pragma unroll
                for (int i = 0; i < 8; i++) {
                    float4 v = Bf[i * 32];
                    sacc[i][0] = v.x; sacc[i][1] = v.y;
                    sacc[i][2] = v.z; sacc[i][3] = v.w;
                }
            }
            #pragma unroll
            for (int kk = 0; kk < 2; kk++) {
                uint32_t af[4];
                {
                    int row = rbase + (lane & 15);
                    int c4 = kk * 2 + (lane >> 4);
                    LDSM_X4(af, Qb + ((row * 32 + ((c4 ^ ((row >> 1) & 3)) << 3)) << 1));
                }
                #pragma unroll
                for (int ntp = 0; ntp < 4; ntp++) {
                    uint32_t bf[4];
                    int row = ntp * 16 + ((lane >> 4) << 3) + (lane & 7);
                    int c4 = kk * 2 + ((lane >> 3) & 1);
                    LDSM_X4(bf, Kb + ((row * 32 + ((c4 ^ ((row >> 1) & 3)) << 3)) << 1));
                    MMA_16816(sacc[ntp * 2],     af, bf[0], bf[1]);
                    MMA_16816(sacc[ntp * 2 + 1], af, bf[2], bf[3]);
                }
            }

            float mx0 = -1e30f, mx1 = -1e30f;
            #pragma unroll
            for (int nt = 0; nt < 8; nt++) {
                mx0 = fmaxf(mx0, fmaxf(sacc[nt][0], sacc[nt][1]));
                mx1 = fmaxf(mx1, fmaxf(sacc[nt][2], sacc[nt][3]));
            }
            mx0 = fmaxf(mx0, __shfl_xor_sync(0xffffffffu, mx0, 1));
            mx0 = fmaxf(mx0, __shfl_xor_sync(0xffffffffu, mx0, 2));
            mx1 = fmaxf(mx1, __shfl_xor_sync(0xffffffffu, mx1, 1));
            mx1 = fmaxf(mx1, __shfl_xor_sync(0xffffffffu, mx1, 2));
            float sum0 = 0.0f, sum1 = 0.0f;
            #pragma unroll
            for (int nt = 0; nt < 8; nt++) {
                sacc[nt][0] = exp2f(sacc[nt][0] - mx0);
                sacc[nt][1] = exp2f(sacc[nt][1] - mx0);
                sacc[nt][2] = exp2f(sacc[nt][2] - mx1);
                sacc[nt][3] = exp2f(sacc[nt][3] - mx1);
                sum0 += sacc[nt][0] + sacc[nt][1];
                sum1 += sacc[nt][2] + sacc[nt][3];
            }
            sum0 += __shfl_xor_sync(0xffffffffu, sum0, 1);
            sum0 += __shfl_xor_sync(0xffffffffu, sum0, 2);
            sum1 += __shfl_xor_sync(0xffffffffu, sum1, 1);
            sum1 += __shfl_xor_sync(0xffffffffu, sum1, 2);
            float inv0 = __fdividef(1.0f, sum0);
            float inv1 = __fdividef(1.0f, sum1);

            float oacc[4][4];
            #pragma unroll
            for (int n4 = 0; n4 < 4; n4++)
                #pragma unroll
                for (int r = 0; r < 4; r++) oacc[n4][r] = 0.0f;

            #pragma unroll
            for (int kk = 0; kk < 4; kk++) {
                uint32_t bf[2][4];
                #pragma unroll
                for (int ntp = 0; ntp < 2; ntp++) {
                    int row = kk * 16 + ((lane >> 3) & 1) * 8 + (lane & 7);
                    int c4 = ntp * 2 + ((lane >> 4) & 1);
                    LDSM_X4_T(bf[ntp], Vb + ((row * 32 + ((c4 ^ ((row >> 1) & 3)) << 3)) << 1));
                }
                uint32_t ah[4], al[4];
                pack_hl(sacc[2 * kk][0],     sacc[2 * kk][1],     ah[0], al[0]);
                pack_hl(sacc[2 * kk][2],     sacc[2 * kk][3],     ah[1], al[1]);
                pack_hl(sacc[2 * kk + 1][0], sacc[2 * kk + 1][1], ah[2], al[2]);
                pack_hl(sacc[2 * kk + 1][2], sacc[2 * kk + 1][3], ah[3], al[3]);
                #pragma unroll
                for (int n4 = 0; n4 < 4; n4++) {
                    MMA_16816(oacc[n4], ah, bf[n4 >> 1][(n4 & 1) * 2], bf[n4 >> 1][(n4 & 1) * 2 + 1]);
                    MMA_16816(oacc[n4], al, bf[n4 >> 1][(n4 & 1) * 2], bf[n4 >> 1][(n4 & 1) * 2 + 1]);
                }
            }

            // packed epilogue: one STG.128 per row (k-permuted layout; g_wpt
            // is permuted identically so out_gemm sees consistent pairs)
            size_t rowg = (size_t)b * 64 + r0;
            const int colp = cbase + (h << 5) + tig * 8;
            uint4 u0, u1;
            {
                __half2 v;
                v = __floats2half2_rn(oacc[0][0] * inv0, oacc[0][1] * inv0); u0.x = *(uint32_t*)&v;
                v = __floats2half2_rn(oacc[1][0] * inv0, oacc[1][1] * inv0); u0.y = *(uint32_t*)&v;
                v = __floats2half2_rn(oacc[2][0] * inv0, oacc[2][1] * inv0); u0.z = *(uint32_t*)&v;
                v = __floats2half2_rn(oacc[3][0] * inv0, oacc[3][1] * inv0); u0.w = *(uint32_t*)&v;
                v = __floats2half2_rn(oacc[0][2] * inv1, oacc[0][3] * inv1); u1.x = *(uint32_t*)&v;
                v = __floats2half2_rn(oacc[1][2] * inv1, oacc[1][3] * inv1); u1.y = *(uint32_t*)&v;
                v = __floats2half2_rn(oacc[2][2] * inv1, oacc[2][3] * inv1); u1.z = *(uint32_t*)&v;
                v = __floats2half2_rn(oacc[3][2] * inv1, oacc[3][3] * inv1); u1.w = *(uint32_t*)&v;
            }
            *(uint4*)(dst0 + rowg * 512 + colp)       = u0;
            *(uint4*)(dst0 + (rowg + 8) * 512 + colp) = u1;
        }
        __syncthreads();
    }
}

// ---------------- output projection GEMM (R15 proven 2-stage) ----------------
#define SM_OUT (98304)

__global__ __launch_bounds__(512, 1)
void out_gemm(const float* __restrict__ bpv, const float* __restrict__ bph,
              float* __restrict__ out) {
    extern __shared__ __half smo[];
    __half* SA = smo;                  // 2 x 8192 halves
    __half* SB = smo + 16384;          // 2 x 16384 halves
    const int mb = blockIdx.x, which = blockIdx.y;
    const __half* A = which ? g_atth : g_attv;
    const __half* B = g_wpt[which];
    const float* bp = which ? bph : bpv;
    float* dst = out + (size_t)which * BNC;

    const int tid = threadIdx.x, w = tid >> 5, lane = tid & 31;
    const int wm = (w >> 2) * 32, wn = (w & 3) * 64;

    float acc[2][8][4];
    #pragma unroll
    for (int t = 0; t < 2; t++)
        #pragma unroll
        for (int j = 0; j < 8; j++)
            #pragma unroll
            for (int r = 0; r < 4; r++) acc[t][j][r] = 0.0f;

    auto issue = [&](int s, int kc) {
        __half* sa = SA + s * 8192;
        __half* sb = SB + s * 16384;
        #pragma unroll
        for (int i = 0; i < 2; i++) {            // A: 1024 chunks of 16B
            int ch = tid + i * 512, r = ch >> 3, k8 = ch & 7;
            uint32_t d = smem_u32(sa + r * 64 + ((k8 ^ (r & 7)) << 3));
            CP_ASYNC16(d, A + (size_t)(mb * 128 + r) * 512 + kc * 64 + k8 * 8);
        }
        #pragma unroll
        for (int i = 0; i < 4; i++) {            // B: 2048 chunks of 16B
            int ch = tid + i * 512, r = ch >> 3, k8 = ch & 7;
            uint32_t d = smem_u32(sb + r * 64 + ((k8 ^ (r & 7)) << 3));
            CP_ASYNC16(d, B + (size_t)r * 512 + kc * 64 + k8 * 8);
        }
    };
    issue(0, 0);
    CP_COMMIT();

    #pragma unroll 1
    for (int kc = 0; kc < 8; kc++) {
        int s = kc & 1;
        if (kc + 1 < 8) {
            issue(s ^ 1, kc + 1);
            CP_COMMIT();
            CP_WAIT(1);
        } else {
            CP_WAIT(0);
        }
        __syncthreads();

        uint32_t baseA = smem_u32(SA + s * 8192);
        uint32_t baseB = smem_u32(SB + s * 16384);
        #pragma unroll
        for (int ks = 0; ks < 4; ks++) {
            uint32_t af[2][4], bf[4][4];
            #pragma unroll
            for (int t = 0; t < 2; t++) {
                int row = wm + t * 16 + (lane & 15);
                int kc8 = ks * 2 + (lane >> 4);
                LDSM_X4(af[t], baseA + ((row * 64 + ((kc8 ^ (row & 7)) << 3)) << 1));
            }
            #pragma unroll
            for (int p = 0; p < 4; p++) {
                int n   = wn + p * 16 + ((lane >> 4) << 3) + (lane & 7);
                int kc8 = ks * 2 + ((lane >> 3) & 1);
                LDSM_X4(bf[p], baseB + ((n * 64 + ((kc8 ^ (n & 7)) << 3)) << 1));
            }
            #pragma unroll
            for (int t = 0; t < 2; t++)
                #pragma unroll
                for (int j = 0; j < 8; j++)
                    MMA_16816(acc[t][j], af[t],
                              bf[j >> 1][(j & 1) * 2], bf[j >> 1][(j & 1) * 2 + 1]);
        }
        __syncthreads();
    }

    const int gid = lane >> 2, tig = lane & 3;
    #pragma unroll
    for (int t = 0; t < 2; t++)
        #pragma unroll
        for (int j = 0; j < 8; j++) {
            int n = wn + j * 8 + tig * 2;             // 0..255
            float b0 = bp[n], b1 = bp[n + 1];
            #pragma unroll
            for (int rr = 0; rr < 2; rr++) {
                int m = mb * 128 + wm + t * 16 + gid + rr * 8;
                float2 v = make_float2(acc[t][j][rr * 2] + b0,
                                       acc[t][j][rr * 2 + 1] + b1);
                *(float2*)(dst + (size_t)m * 256 + n) = v;
            }
        }
}

// ---------------- launch -----------------------------------------------------
// 5 launches: prep_ab, prep_c, qkv, attn (4th = ncu target), out.
extern "C" void kernel_launch(void* const* d_in, const int* in_sizes, int n_in,
                              void* d_out, int out_size) {
    const float* input_x = (const float*)d_in[0];
    const float* state_x = (const float*)d_in[1];
    const float* Ws  = (const float*)d_in[2];
    const float* bs  = (const float*)d_in[3];
    const float* We  = (const float*)d_in[4];
    const float* be  = (const float*)d_in[5];
    const float* Wpv = (const float*)d_in[6];
    const float* bpv = (const float*)d_in[7];
    const float* Wph = (const float*)d_in[8];
    const float* bph = (const float*)d_in[9];
    const float* tcv = (const float*)d_in[10];
    const float* tsv = (const float*)d_in[11];
    const float* tch = (const float*)d_in[12];
    const float* tsh = (const float*)d_in[13];
    const int*   rpi = (const int*)d_in[14];
    float* out = (float*)d_out;

    cudaFuncSetAttribute(qkv_gemm, cudaFuncAttributeMaxDynamicSharedMemorySize, SM_QKV);
    cudaFuncSetAttribute(attn_kernel, cudaFuncAttributeMaxDynamicSharedMemorySize, SM_ATT);
    cudaFuncSetAttribute(out_gemm, cudaFuncAttributeMaxDynamicSharedMemorySize, SM_OUT);

    prep_ab<<<2560, 256>>>(Ws, We, tcv, tsv, tch, tsh, rpi);               // 1
    prep_c<<<1024, 256>>>(Wpv, Wph);                                       // 2
    qkv_gemm<<<dim3(1024, 2), 512, SM_QKV>>>(input_x, state_x, bs, be);    // 3
    attn_kernel<<<NWIN, 256, SM_ATT>>>();                                  // 4 <- ncu
    out_gemm<<<dim3(1024, 2), 512, SM_OUT>>>(bpv, bph, out);               // 5
}